// round 10
// baseline (speedup 1.0000x reference)
#include <cuda_runtime.h>
#include <cuda_bf16.h>
#include <math.h>
#include <stdint.h>

#define N_NODES 50000
#define N_EDGES 800000
#define EP      (N_EDGES + N_NODES)   // with self loops = 850000
#define GGR     512
#define HID     64

// ---------------- scratch (device globals; no allocs allowed) ----------------
__device__ float    g_z[N_NODES * 256];
__device__ float    g_h[N_NODES * 256];
__device__ __nv_bfloat16 g_Ahi[N_NODES * 256];
__device__ __nv_bfloat16 g_Alo[N_NODES * 256];
__device__ __nv_bfloat16 g_Bh[96 * 1024];   // W0@0, W1@16384, W2@81920
__device__ __nv_bfloat16 g_Bl[96 * 1024];
__device__ float    g_as[N_NODES * 4];
__device__ float    g_ad[N_NODES * 4];
__device__ int      g_rowptr[N_NODES + 1];
__device__ int      g_cursor[N_NODES];
__device__ int      g_cnt[N_NODES];
__device__ int      g_srcs[EP];

// ---------------- small helpers ----------------
__device__ __forceinline__ uint32_t cvta_s(const void* p) {
    uint32_t a;
    asm("{ .reg .u64 t; cvta.to.shared.u64 t, %1; cvt.u32.u64 %0, t; }" : "=r"(a) : "l"(p));
    return a;
}
__device__ __forceinline__ void cp_async16(uint32_t dst, const void* src, unsigned sz) {
    asm volatile("cp.async.ca.shared.global [%0], [%1], 16, %2;"
                 :: "r"(dst), "l"(src), "r"(sz));
}
#define CP_COMMIT() asm volatile("cp.async.commit_group;" ::: "memory")
#define CP_WAIT1()  asm volatile("cp.async.wait_group 1;" ::: "memory")

// ---------------- CSR build ----------------
__global__ void k_zero_cnt(int* cnt) {
    int i = blockIdx.x * blockDim.x + threadIdx.x;
    if (i < N_NODES) cnt[i] = 0;
}

__global__ void k_hist(const int* __restrict__ ei, int* cnt) {
    int i = blockIdx.x * blockDim.x + threadIdx.x;
    if (i >= EP) return;
    int d = (i < N_EDGES) ? ei[N_EDGES + i] : (i - N_EDGES);
    atomicAdd(&cnt[d], 1);
}

// fast single-block scan: per-thread serial prefix + one warp/block shfl scan
__global__ void k_scan(const int* __restrict__ cnt, int* rowptr, int* cursor) {
    const int n = N_NODES;
    const int t = threadIdx.x;              // 1024 threads
    const int per = (n + 1023) / 1024;      // 49
    int b = t * per;
    int e = b + per; if (e > n) e = n;
    int sum = 0;
    for (int i = b; i < e; i++) sum += cnt[i];

    __shared__ int ws[32];
    int lane = t & 31, w = t >> 5;
    int inc = sum;
#pragma unroll
    for (int o = 1; o < 32; o <<= 1) {
        int v = __shfl_up_sync(0xffffffffu, inc, o);
        if (lane >= o) inc += v;
    }
    if (lane == 31) ws[w] = inc;
    __syncthreads();
    if (w == 0) {
        int iv = ws[lane];
#pragma unroll
        for (int o = 1; o < 32; o <<= 1) {
            int u = __shfl_up_sync(0xffffffffu, iv, o);
            if (lane >= o) iv += u;
        }
        ws[lane] = iv;
    }
    __syncthreads();
    int run = inc - sum + (w ? ws[w - 1] : 0);
    for (int i = b; i < e; i++) {
        rowptr[i] = run; cursor[i] = run;
        run += cnt[i];
    }
    if (b < n && e == n) rowptr[n] = run;
}

__global__ void k_scatter(const int* __restrict__ ei, int* cursor, int* srcs) {
    int i = blockIdx.x * blockDim.x + threadIdx.x;
    if (i >= EP) return;
    int s, d;
    if (i < N_EDGES) { s = ei[i]; d = ei[N_EDGES + i]; }
    else             { s = d = i - N_EDGES; }
    int p = atomicAdd(&cursor[d], 1);
    srcs[p] = s;
}

// ---------------- bf16 split helpers ----------------
__global__ void k_split(const float* __restrict__ a, __nv_bfloat16* __restrict__ hi,
                        __nv_bfloat16* __restrict__ lo, int n) {
    int i = blockIdx.x * blockDim.x + threadIdx.x;
    if (i >= n) return;
    float v = a[i];
    __nv_bfloat16 h = __float2bfloat16(v);
    hi[i] = h;
    lo[i] = __float2bfloat16(v - __bfloat162float(h));
}

// W[K,NC] row-major -> Bt[NC,K] hi/lo (col-major B for mma.sync)
__global__ void k_wsplit(const float* __restrict__ w, __nv_bfloat16* __restrict__ bh,
                         __nv_bfloat16* __restrict__ bl, int K, int NC) {
    int i = blockIdx.x * blockDim.x + threadIdx.x;
    if (i >= K * NC) return;
    int k = i / NC, n = i - k * NC;
    float v = w[i];
    __nv_bfloat16 h = __float2bfloat16(v);
    bh[n * K + k] = h;
    bl[n * K + k] = __float2bfloat16(v - __bfloat162float(h));
}

// ---------------- HMMA GEMM + fused attention coefficients ----------------
__device__ __forceinline__ void mma_bf16(float* d, const uint32_t* a, const uint32_t* b) {
    asm volatile(
        "mma.sync.aligned.m16n8k16.row.col.f32.bf16.bf16.f32 "
        "{%0,%1,%2,%3}, {%4,%5,%6,%7}, {%8,%9}, {%0,%1,%2,%3};"
        : "+f"(d[0]), "+f"(d[1]), "+f"(d[2]), "+f"(d[3])
        : "r"(a[0]), "r"(a[1]), "r"(a[2]), "r"(a[3]), "r"(b[0]), "r"(b[1]));
}

template <int K, int NC>
__global__ void __launch_bounds__(256) k_gemm_mma(
    const __nv_bfloat16* __restrict__ Ahi, const __nv_bfloat16* __restrict__ Alo,
    const __nv_bfloat16* __restrict__ Bhi, const __nv_bfloat16* __restrict__ Blo,
    const float* __restrict__ ASrc, const float* __restrict__ ADst,
    float* __restrict__ Cm, float* __restrict__ as_, float* __restrict__ ad_, int M)
{
    extern __shared__ char smc[];
    constexpr int AST  = 40;           // smem row stride in bf16
    constexpr int ABYT = 128 * AST * 2;   // 10240
    constexpr int BBYT = 64 * AST * 2;    // 5120
    constexpr int OFF_AH = 0;
    constexpr int OFF_AL = 2 * ABYT;
    constexpr int OFF_BH = 4 * ABYT;
    constexpr int OFF_BL = 4 * ABYT + 2 * BBYT;
    constexpr int CHUNKS = K / 32;

    const int tid  = threadIdx.x;
    const int lane = tid & 31;
    const int wid  = tid >> 5;
    const int wm   = wid & 3;
    const int wn   = wid >> 2;
    const int rowBase = blockIdx.x * 128;
    const int colBase = blockIdx.y * 64;
    const int g   = lane >> 2;
    const int tig = lane & 3;
    const uint32_t sbase = cvta_s(smc);

    float d[2][4][4];
#pragma unroll
    for (int mi = 0; mi < 2; mi++)
#pragma unroll
        for (int ni = 0; ni < 4; ni++)
#pragma unroll
            for (int q = 0; q < 4; q++) d[mi][ni][q] = 0.f;

    auto load_chunk = [&](int k0, int st) {
        uint32_t aH = sbase + OFF_AH + st * ABYT;
        uint32_t aL = sbase + OFF_AL + st * ABYT;
        uint32_t bH = sbase + OFF_BH + st * BBYT;
        uint32_t bL = sbase + OFF_BL + st * BBYT;
#pragma unroll
        for (int j = 0; j < 2; j++) {
            int i = tid + j * 256;       // 0..511
            int r = i >> 2, q = i & 3;
            int grow = rowBase + r;
            int cg = (grow < M) ? grow : 0;
            unsigned sz = (grow < M) ? 16u : 0u;
            size_t so = ((size_t)cg * K + k0) * 2 + q * 16;
            uint32_t dst = r * 80 + q * 16;
            cp_async16(aH + dst, (const char*)Ahi + so, sz);
            cp_async16(aL + dst, (const char*)Alo + so, sz);
        }
        {
            int r = tid >> 2, q = tid & 3;   // 64 rows x 4
            size_t so = ((size_t)(colBase + r) * K + k0) * 2 + q * 16;
            uint32_t dst = r * 80 + q * 16;
            cp_async16(bH + dst, (const char*)Bhi + so, 16u);
            cp_async16(bL + dst, (const char*)Blo + so, 16u);
        }
    };

    load_chunk(0, 0);
    CP_COMMIT();

    for (int c = 0; c < CHUNKS; c++) {
        if (c + 1 < CHUNKS) load_chunk((c + 1) * 32, (c + 1) & 1);
        CP_COMMIT();
        CP_WAIT1();
        __syncthreads();
        const int st = c & 1;
        const char* pAh = smc + OFF_AH + st * ABYT;
        const char* pAl = smc + OFF_AL + st * ABYT;
        const char* pBh = smc + OFF_BH + st * BBYT;
        const char* pBl = smc + OFF_BL + st * BBYT;
#pragma unroll
        for (int ks = 0; ks < 32; ks += 16) {
            uint32_t ah[2][4], al[2][4], bh[4][2], bl[4][2];
#pragma unroll
            for (int mi = 0; mi < 2; mi++) {
                int r0 = ((wm * 32 + mi * 16 + g) * AST + ks + 2 * tig) * 2;
                int r8 = r0 + 8 * AST * 2;
                ah[mi][0] = *(const uint32_t*)(pAh + r0);
                ah[mi][1] = *(const uint32_t*)(pAh + r8);
                ah[mi][2] = *(const uint32_t*)(pAh + r0 + 16);
                ah[mi][3] = *(const uint32_t*)(pAh + r8 + 16);
                al[mi][0] = *(const uint32_t*)(pAl + r0);
                al[mi][1] = *(const uint32_t*)(pAl + r8);
                al[mi][2] = *(const uint32_t*)(pAl + r0 + 16);
                al[mi][3] = *(const uint32_t*)(pAl + r8 + 16);
            }
#pragma unroll
            for (int ni = 0; ni < 4; ni++) {
                int br = ((wn * 32 + ni * 8 + g) * AST + ks + 2 * tig) * 2;
                bh[ni][0] = *(const uint32_t*)(pBh + br);
                bh[ni][1] = *(const uint32_t*)(pBh + br + 16);
                bl[ni][0] = *(const uint32_t*)(pBl + br);
                bl[ni][1] = *(const uint32_t*)(pBl + br + 16);
            }
#pragma unroll
            for (int mi = 0; mi < 2; mi++)
#pragma unroll
                for (int ni = 0; ni < 4; ni++) {
                    mma_bf16(d[mi][ni], ah[mi], bh[ni]);
                    mma_bf16(d[mi][ni], ah[mi], bl[ni]);
                    mma_bf16(d[mi][ni], al[mi], bh[ni]);
                }
        }
        __syncthreads();
    }

    // ---- write C
#pragma unroll
    for (int mi = 0; mi < 2; mi++) {
        int row0 = rowBase + wm * 32 + mi * 16 + g;
        int row8 = row0 + 8;
#pragma unroll
        for (int ni = 0; ni < 4; ni++) {
            int col = colBase + wn * 32 + ni * 8 + 2 * tig;
            if (row0 < M) {
                float2* p = (float2*)(Cm + (size_t)row0 * NC + col);
                *p = make_float2(d[mi][ni][0], d[mi][ni][1]);
            }
            if (row8 < M) {
                float2* p = (float2*)(Cm + (size_t)row8 * NC + col);
                *p = make_float2(d[mi][ni][2], d[mi][ni][3]);
            }
        }
    }

    // ---- fused attention coefficients for this block's 128 rows / 1 head
    const int head = (NC == 256) ? blockIdx.y : 0;
    float asv[4][2], adv[4][2];
#pragma unroll
    for (int ni = 0; ni < 4; ni++)
#pragma unroll
        for (int q = 0; q < 2; q++) {
            int c = wn * 32 + ni * 8 + 2 * tig + q;
            asv[ni][q] = ASrc[head * 64 + c];
            adv[ni][q] = ADst[head * 64 + c];
        }
    float vs[2][2], vd[2][2];
#pragma unroll
    for (int mi = 0; mi < 2; mi++)
#pragma unroll
        for (int hf = 0; hf < 2; hf++) {
            float ss = 0.f, dd = 0.f;
#pragma unroll
            for (int ni = 0; ni < 4; ni++) {
                ss += d[mi][ni][2 * hf] * asv[ni][0] + d[mi][ni][2 * hf + 1] * asv[ni][1];
                dd += d[mi][ni][2 * hf] * adv[ni][0] + d[mi][ni][2 * hf + 1] * adv[ni][1];
            }
#pragma unroll
            for (int off = 1; off < 4; off <<= 1) {
                ss += __shfl_xor_sync(0xffffffffu, ss, off);
                dd += __shfl_xor_sync(0xffffffffu, dd, off);
            }
            vs[mi][hf] = ss; vd[mi][hf] = dd;
        }
    float* sAS = (float*)smc;          // 128 floats
    float* sAD = (float*)(smc + 512);  // 128 floats
    __syncthreads();
    if (wn == 1 && tig == 0) {
#pragma unroll
        for (int mi = 0; mi < 2; mi++)
#pragma unroll
            for (int hf = 0; hf < 2; hf++) {
                int row = wm * 32 + mi * 16 + g + 8 * hf;
                sAS[row] = vs[mi][hf];
                sAD[row] = vd[mi][hf];
            }
    }
    __syncthreads();
    if (wn == 0 && tig == 0) {
#pragma unroll
        for (int mi = 0; mi < 2; mi++)
#pragma unroll
            for (int hf = 0; hf < 2; hf++) {
                int row = wm * 32 + mi * 16 + g + 8 * hf;
                int grow = rowBase + row;
                if (grow < M) {
                    float ts = vs[mi][hf] + sAS[row];
                    float td = vd[mi][hf] + sAD[row];
                    if (NC == 256) { as_[grow * 4 + head] = ts; ad_[grow * 4 + head] = td; }
                    else           { as_[grow] = ts; ad_[grow] = td; }
                }
            }
    }
}

// ---------------- warp-per-node softmax + aggregation ----------------
// SPLIT layers write ONLY the bf16 hi/lo splits (the fp32 out is never read).
template <int H, bool ELU, bool SPLIT>
__global__ void __launch_bounds__(256) k_agg_warp(
    const float* __restrict__ z, const int* __restrict__ srcs,
    const int* __restrict__ rowptr, const float* __restrict__ as_,
    const float* __restrict__ ad_, const float* __restrict__ bias,
    float* __restrict__ out,
    __nv_bfloat16* __restrict__ ohi, __nv_bfloat16* __restrict__ olo)
{
    __shared__ int   s_src[8][32];
    __shared__ float s_alpha[8][32 * H];

    const int wid  = threadIdx.x >> 5;
    const int lane = threadIdx.x & 31;
    const int n = blockIdx.x * 8 + wid;
    if (n >= N_NODES) return;

    const int start = rowptr[n];
    const int deg = rowptr[n + 1] - start;

    float m[H], s[H];
    float adv[H];
    if (H == 4) {
        float4 a = *(const float4*)(ad_ + n * 4);
        adv[0] = a.x; adv[1] = a.y; adv[2] = a.z; adv[3] = a.w;
    } else {
        adv[0] = ad_[n];
    }
#pragma unroll
    for (int h = 0; h < H; h++) { m[h] = -1e30f; s[h] = 0.f; }
    for (int j = lane; j < deg; j += 32) {
        int sidx = srcs[start + j];
        if (H == 4) {
            float4 av = *(const float4*)(as_ + sidx * 4);
            float ev[4] = {av.x, av.y, av.z, av.w};
#pragma unroll
            for (int h = 0; h < 4; h++) {
                float e = ev[h] + adv[h];
                e = (e > 0.f) ? e : 0.2f * e;
                float nm = fmaxf(m[h], e);
                s[h] = s[h] * __expf(m[h] - nm) + __expf(e - nm);
                m[h] = nm;
            }
        } else {
            float e = as_[sidx] + adv[0];
            e = (e > 0.f) ? e : 0.2f * e;
            float nm = fmaxf(m[0], e);
            s[0] = s[0] * __expf(m[0] - nm) + __expf(e - nm);
            m[0] = nm;
        }
    }
#pragma unroll
    for (int off = 16; off; off >>= 1) {
#pragma unroll
        for (int h = 0; h < H; h++) {
            float mo = __shfl_xor_sync(0xffffffffu, m[h], off);
            float so = __shfl_xor_sync(0xffffffffu, s[h], off);
            float nm = fmaxf(m[h], mo);
            s[h] = s[h] * __expf(m[h] - nm) + so * __expf(mo - nm);
            m[h] = nm;
        }
    }
#pragma unroll
    for (int h = 0; h < H; h++) s[h] = 1.0f / (s[h] + 1e-16f);

    float4 acc0 = make_float4(0.f, 0.f, 0.f, 0.f);
    float4 acc1 = make_float4(0.f, 0.f, 0.f, 0.f);
    float2 accs = make_float2(0.f, 0.f);
    const int head0 = lane >> 4;
    for (int base = 0; base < deg; base += 32) {
        int len = min(32, deg - base);
        if (lane < len) {
            int sidx = srcs[start + base + lane];
            s_src[wid][lane] = sidx;
            if (H == 4) {
                float4 av = *(const float4*)(as_ + sidx * 4);
                float ev[4] = {av.x, av.y, av.z, av.w};
                float al[4];
#pragma unroll
                for (int h = 0; h < 4; h++) {
                    float e = ev[h] + adv[h];
                    e = (e > 0.f) ? e : 0.2f * e;
                    al[h] = __expf(e - m[h]) * s[h];
                }
                *(float4*)&s_alpha[wid][lane * 4] = make_float4(al[0], al[1], al[2], al[3]);
            } else {
                float e = as_[sidx] + adv[0];
                e = (e > 0.f) ? e : 0.2f * e;
                s_alpha[wid][lane] = __expf(e - m[0]) * s[0];
            }
        }
        __syncwarp();
        if (H == 4) {
            for (int j = 0; j < len; j++) {
                int sidx = s_src[wid][j];
                float a0 = s_alpha[wid][j * 4 + head0];
                float a1 = s_alpha[wid][j * 4 + 2 + head0];
                const float4* zp = (const float4*)(z + (size_t)sidx * 256);
                float4 z0 = zp[lane];
                float4 z1 = zp[32 + lane];
                acc0.x = fmaf(a0, z0.x, acc0.x);
                acc0.y = fmaf(a0, z0.y, acc0.y);
                acc0.z = fmaf(a0, z0.z, acc0.z);
                acc0.w = fmaf(a0, z0.w, acc0.w);
                acc1.x = fmaf(a1, z1.x, acc1.x);
                acc1.y = fmaf(a1, z1.y, acc1.y);
                acc1.z = fmaf(a1, z1.z, acc1.z);
                acc1.w = fmaf(a1, z1.w, acc1.w);
            }
        } else {
            for (int j = 0; j < len; j++) {
                int sidx = s_src[wid][j];
                float a = s_alpha[wid][j];
                float2 zv = *(const float2*)(z + (size_t)sidx * 64 + lane * 2);
                accs.x = fmaf(a, zv.x, accs.x);
                accs.y = fmaf(a, zv.y, accs.y);
            }
        }
        __syncwarp();
    }

    if (H == 4) {
        float4 b0 = ((const float4*)bias)[lane];
        float4 b1 = ((const float4*)bias)[32 + lane];
        acc0.x += b0.x; acc0.y += b0.y; acc0.z += b0.z; acc0.w += b0.w;
        acc1.x += b1.x; acc1.y += b1.y; acc1.z += b1.z; acc1.w += b1.w;
        if (ELU) {
            acc0.x = (acc0.x > 0.f) ? acc0.x : expm1f(acc0.x);
            acc0.y = (acc0.y > 0.f) ? acc0.y : expm1f(acc0.y);
            acc0.z = (acc0.z > 0.f) ? acc0.z : expm1f(acc0.z);
            acc0.w = (acc0.w > 0.f) ? acc0.w : expm1f(acc0.w);
            acc1.x = (acc1.x > 0.f) ? acc1.x : expm1f(acc1.x);
            acc1.y = (acc1.y > 0.f) ? acc1.y : expm1f(acc1.y);
            acc1.z = (acc1.z > 0.f) ? acc1.z : expm1f(acc1.z);
            acc1.w = (acc1.w > 0.f) ? acc1.w : expm1f(acc1.w);
        }
        if (!SPLIT) {
            float4* po = (float4*)(out + (size_t)n * 256);
            po[lane] = acc0;
            po[32 + lane] = acc1;
        } else {
            __nv_bfloat16 h0x = __float2bfloat16(acc0.x), h0y = __float2bfloat16(acc0.y);
            __nv_bfloat16 h0z = __float2bfloat16(acc0.z), h0w = __float2bfloat16(acc0.w);
            __nv_bfloat16 h1x = __float2bfloat16(acc1.x), h1y = __float2bfloat16(acc1.y);
            __nv_bfloat16 h1z = __float2bfloat16(acc1.z), h1w = __float2bfloat16(acc1.w);
            __nv_bfloat162* ph = (__nv_bfloat162*)(ohi + (size_t)n * 256);
            __nv_bfloat162* pl = (__nv_bfloat162*)(olo + (size_t)n * 256);
            ph[2 * lane]     = __nv_bfloat162(h0x, h0y);
            ph[2 * lane + 1] = __nv_bfloat162(h0z, h0w);
            ph[64 + 2 * lane]     = __nv_bfloat162(h1x, h1y);
            ph[64 + 2 * lane + 1] = __nv_bfloat162(h1z, h1w);
            pl[2 * lane]     = __nv_bfloat162(__float2bfloat16(acc0.x - __bfloat162float(h0x)),
                                              __float2bfloat16(acc0.y - __bfloat162float(h0y)));
            pl[2 * lane + 1] = __nv_bfloat162(__float2bfloat16(acc0.z - __bfloat162float(h0z)),
                                              __float2bfloat16(acc0.w - __bfloat162float(h0w)));
            pl[64 + 2 * lane]     = __nv_bfloat162(__float2bfloat16(acc1.x - __bfloat162float(h1x)),
                                                   __float2bfloat16(acc1.y - __bfloat162float(h1y)));
            pl[64 + 2 * lane + 1] = __nv_bfloat162(__float2bfloat16(acc1.z - __bfloat162float(h1z)),
                                                   __float2bfloat16(acc1.w - __bfloat162float(h1w)));
        }
    } else {
        float2 b = ((const float2*)bias)[lane];
        accs.x += b.x; accs.y += b.y;
        if (ELU) {
            accs.x = (accs.x > 0.f) ? accs.x : expm1f(accs.x);
            accs.y = (accs.y > 0.f) ? accs.y : expm1f(accs.y);
        }
        *(float2*)(out + (size_t)n * 64 + lane * 2) = accs;
    }
}

// ---------------- segmented global max pool (batch is sorted) ----------------
__global__ void __launch_bounds__(256) k_pool_seg(
    const float* __restrict__ hfin, const int* __restrict__ batch,
    float* __restrict__ out)
{
    __shared__ float s_red[256];
    __shared__ int s_bounds[2];
    const int g = blockIdx.x;
    const int t = threadIdx.x;
    if (t < 2) {
        int target = g + t;
        int lo = 0, hi = N_NODES;
        while (lo < hi) {
            int mid = (lo + hi) >> 1;
            if (batch[mid] < target) lo = mid + 1; else hi = mid;
        }
        s_bounds[t] = lo;
    }
    __syncthreads();
    const int n0 = s_bounds[0], n1 = s_bounds[1];
    const int c = t & 63;
    const int sub = t >> 6;   // 0..3
    float acc = -1e30f;
    for (int n = n0 + sub; n < n1; n += 4)
        acc = fmaxf(acc, hfin[(size_t)n * 64 + c]);
    s_red[t] = acc;
    __syncthreads();
    if (t < 64) {
        float v = fmaxf(fmaxf(s_red[t], s_red[t + 64]),
                        fmaxf(s_red[t + 128], s_red[t + 192]));
        out[g * 64 + c] = v;
    }
}

// ---------------- launch ----------------
extern "C" void kernel_launch(void* const* d_in, const int* in_sizes, int n_in,
                              void* d_out, int out_size) {
    const float* x     = (const float*)d_in[0];
    const int*   ei    = (const int*)d_in[1];
    const int*   batch = (const int*)d_in[2];
    const float* W0    = (const float*)d_in[3];
    const float* AS0   = (const float*)d_in[4];
    const float* AD0   = (const float*)d_in[5];
    const float* B0    = (const float*)d_in[6];
    const float* W1    = (const float*)d_in[7];
    const float* AS1   = (const float*)d_in[8];
    const float* AD1   = (const float*)d_in[9];
    const float* B1    = (const float*)d_in[10];
    const float* W2    = (const float*)d_in[11];
    const float* AS2   = (const float*)d_in[12];
    const float* AD2   = (const float*)d_in[13];
    const float* B2    = (const float*)d_in[14];

    float *z, *h, *as_, *ad_;
    __nv_bfloat16 *ahi, *alo, *bh, *bl;
    int *rowptr, *cursor, *cnt, *srcs;
    cudaGetSymbolAddress((void**)&z, g_z);
    cudaGetSymbolAddress((void**)&h, g_h);
    cudaGetSymbolAddress((void**)&ahi, g_Ahi);
    cudaGetSymbolAddress((void**)&alo, g_Alo);
    cudaGetSymbolAddress((void**)&bh, g_Bh);
    cudaGetSymbolAddress((void**)&bl, g_Bl);
    cudaGetSymbolAddress((void**)&as_, g_as);
    cudaGetSymbolAddress((void**)&ad_, g_ad);
    cudaGetSymbolAddress((void**)&rowptr, g_rowptr);
    cudaGetSymbolAddress((void**)&cursor, g_cursor);
    cudaGetSymbolAddress((void**)&cnt, g_cnt);
    cudaGetSymbolAddress((void**)&srcs, g_srcs);

    // per-layer W buffer regions (hi/lo)
    __nv_bfloat16* bh0 = bh;            __nv_bfloat16* bl0 = bl;
    __nv_bfloat16* bh1 = bh + 16384;    __nv_bfloat16* bl1 = bl + 16384;
    __nv_bfloat16* bh2 = bh + 81920;    __nv_bfloat16* bl2 = bl + 81920;

    const int M = N_NODES;
    const int GEMM_GRID = (M + 127) / 128;   // 391
    const int AGG_GRID  = (N_NODES + 7) / 8; // warp-per-node, 8 warps/block
    const int GSMEM = 4 * 10240 + 4 * 5120;  // 61440 bytes

    cudaFuncSetAttribute(k_gemm_mma<64, 256>,  cudaFuncAttributeMaxDynamicSharedMemorySize, GSMEM);
    cudaFuncSetAttribute(k_gemm_mma<256, 256>, cudaFuncAttributeMaxDynamicSharedMemorySize, GSMEM);
    cudaFuncSetAttribute(k_gemm_mma<256, 64>,  cudaFuncAttributeMaxDynamicSharedMemorySize, GSMEM);

    // side stream + events (created once; launch pattern identical every call)
    static cudaStream_t sSide = nullptr;
    static cudaEvent_t  evRoot = nullptr, evSide = nullptr;
    if (!sSide) {
        cudaStreamCreateWithFlags(&sSide, cudaStreamNonBlocking);
        cudaEventCreateWithFlags(&evRoot, cudaEventDisableTiming);
        cudaEventCreateWithFlags(&evSide, cudaEventDisableTiming);
    }

    // ---- fork: CSR build + wsplit1/2 on side stream
    cudaEventRecord(evRoot, 0);
    cudaStreamWaitEvent(sSide, evRoot, 0);
    k_zero_cnt<<<(N_NODES + 255) / 256, 256, 0, sSide>>>(cnt);
    k_hist<<<(EP + 255) / 256, 256, 0, sSide>>>(ei, cnt);
    k_scan<<<1, 1024, 0, sSide>>>(cnt, rowptr, cursor);
    k_scatter<<<(EP + 255) / 256, 256, 0, sSide>>>(ei, cursor, srcs);
    k_wsplit<<<(256 * 256 + 255) / 256, 256, 0, sSide>>>(W1, bh1, bl1, 256, 256);
    k_wsplit<<<(256 * 64 + 255) / 256, 256, 0, sSide>>>(W2, bh2, bl2, 256, 64);
    cudaEventRecord(evSide, sSide);

    // ---- main stream: layer-0 prep + GEMM (independent of CSR)
    k_split<<<(N_NODES * 64 + 255) / 256, 256>>>(x, ahi, alo, N_NODES * 64);
    k_wsplit<<<(64 * 256 + 255) / 256, 256>>>(W0, bh0, bl0, 64, 256);
    k_gemm_mma<64, 256><<<dim3(GEMM_GRID, 4), 256, GSMEM>>>(ahi, alo, bh0, bl0, AS0, AD0, z, as_, ad_, M);

    // ---- join: agg needs CSR (and later layers need wsplit1/2)
    cudaStreamWaitEvent(0, evSide, 0);
    k_agg_warp<4, true, true><<<AGG_GRID, 256>>>(z, srcs, rowptr, as_, ad_, B0, h, ahi, alo);

    // ---- layer 1
    k_gemm_mma<256, 256><<<dim3(GEMM_GRID, 4), 256, GSMEM>>>(ahi, alo, bh1, bl1, AS1, AD1, z, as_, ad_, M);
    k_agg_warp<4, true, true><<<AGG_GRID, 256>>>(z, srcs, rowptr, as_, ad_, B1, h, ahi, alo);

    // ---- layer 2
    k_gemm_mma<256, 64><<<dim3(GEMM_GRID, 1), 256, GSMEM>>>(ahi, alo, bh2, bl2, AS2, AD2, z, as_, ad_, M);
    k_agg_warp<1, false, false><<<AGG_GRID, 256>>>(z, srcs, rowptr, as_, ad_, B2, h, (__nv_bfloat16*)0, (__nv_bfloat16*)0);

    // ---- segmented max pool
    k_pool_seg<<<GGR, 256>>>(h, batch, (float*)d_out);
}

// round 13
// speedup vs baseline: 1.4583x; 1.4583x over previous
#include <cuda_runtime.h>
#include <cuda_bf16.h>
#include <math.h>
#include <stdint.h>

#define N_NODES 50000
#define N_EDGES 800000
#define EP      (N_EDGES + N_NODES)   // with self loops = 850000
#define GGR     512
#define HID     64

// ---------------- scratch (device globals; no allocs allowed) ----------------
__device__ float    g_z[N_NODES * 256];
__device__ float    g_h[N_NODES * 256];
__device__ __nv_bfloat16 g_Ahi[N_NODES * 256];
__device__ __nv_bfloat16 g_Alo[N_NODES * 256];
__device__ __nv_bfloat16 g_Bh[96 * 1024];   // W0@0, W1@16384, W2@81920
__device__ __nv_bfloat16 g_Bl[96 * 1024];
__device__ float    g_as[N_NODES * 4];
__device__ float    g_ad[N_NODES * 4];
__device__ int      g_rowptr[N_NODES + 1];
__device__ int      g_cursor[N_NODES];
__device__ int      g_cnt[N_NODES];
__device__ int      g_srcs[EP];

// ---------------- small helpers ----------------
__device__ __forceinline__ uint32_t cvta_s(const void* p) {
    uint32_t a;
    asm("{ .reg .u64 t; cvta.to.shared.u64 t, %1; cvt.u32.u64 %0, t; }" : "=r"(a) : "l"(p));
    return a;
}
__device__ __forceinline__ void cp_async16(uint32_t dst, const void* src, unsigned sz) {
    asm volatile("cp.async.ca.shared.global [%0], [%1], 16, %2;"
                 :: "r"(dst), "l"(src), "r"(sz));
}
#define CP_COMMIT() asm volatile("cp.async.commit_group;" ::: "memory")
#define CP_WAIT1()  asm volatile("cp.async.wait_group 1;" ::: "memory")

// ---------------- CSR build ----------------
__global__ void k_zero_cnt(int* cnt) {
    int i = blockIdx.x * blockDim.x + threadIdx.x;
    if (i < N_NODES) cnt[i] = 0;
}

__global__ void k_hist(const int* __restrict__ ei, int* cnt) {
    int i = blockIdx.x * blockDim.x + threadIdx.x;
    if (i >= EP) return;
    int d = (i < N_EDGES) ? ei[N_EDGES + i] : (i - N_EDGES);
    atomicAdd(&cnt[d], 1);
}

// fast single-block scan: per-thread serial prefix + one warp/block shfl scan
__global__ void k_scan(const int* __restrict__ cnt, int* rowptr, int* cursor) {
    const int n = N_NODES;
    const int t = threadIdx.x;              // 1024 threads
    const int per = (n + 1023) / 1024;      // 49
    int b = t * per;
    int e = b + per; if (e > n) e = n;
    int sum = 0;
    for (int i = b; i < e; i++) sum += cnt[i];

    __shared__ int ws[32];
    int lane = t & 31, w = t >> 5;
    int inc = sum;
#pragma unroll
    for (int o = 1; o < 32; o <<= 1) {
        int v = __shfl_up_sync(0xffffffffu, inc, o);
        if (lane >= o) inc += v;
    }
    if (lane == 31) ws[w] = inc;
    __syncthreads();
    if (w == 0) {
        int iv = ws[lane];
#pragma unroll
        for (int o = 1; o < 32; o <<= 1) {
            int u = __shfl_up_sync(0xffffffffu, iv, o);
            if (lane >= o) iv += u;
        }
        ws[lane] = iv;
    }
    __syncthreads();
    int run = inc - sum + (w ? ws[w - 1] : 0);
    for (int i = b; i < e; i++) {
        rowptr[i] = run; cursor[i] = run;
        run += cnt[i];
    }
    if (b < n && e == n) rowptr[n] = run;
}

__global__ void k_scatter(const int* __restrict__ ei, int* cursor, int* srcs) {
    int i = blockIdx.x * blockDim.x + threadIdx.x;
    if (i >= EP) return;
    int s, d;
    if (i < N_EDGES) { s = ei[i]; d = ei[N_EDGES + i]; }
    else             { s = d = i - N_EDGES; }
    int p = atomicAdd(&cursor[d], 1);
    srcs[p] = s;
}

// ---------------- bf16 split helpers ----------------
__global__ void k_split(const float* __restrict__ a, __nv_bfloat16* __restrict__ hi,
                        __nv_bfloat16* __restrict__ lo, int n) {
    int i = blockIdx.x * blockDim.x + threadIdx.x;
    if (i >= n) return;
    float v = a[i];
    __nv_bfloat16 h = __float2bfloat16(v);
    hi[i] = h;
    lo[i] = __float2bfloat16(v - __bfloat162float(h));
}

// W[K,NC] row-major -> Bt[NC,K] hi/lo (col-major B for mma.sync)
__global__ void k_wsplit(const float* __restrict__ w, __nv_bfloat16* __restrict__ bh,
                         __nv_bfloat16* __restrict__ bl, int K, int NC) {
    int i = blockIdx.x * blockDim.x + threadIdx.x;
    if (i >= K * NC) return;
    int k = i / NC, n = i - k * NC;
    float v = w[i];
    __nv_bfloat16 h = __float2bfloat16(v);
    bh[n * K + k] = h;
    bl[n * K + k] = __float2bfloat16(v - __bfloat162float(h));
}

// ---------------- HMMA GEMM + fused attention coefficients ----------------
__device__ __forceinline__ void mma_bf16(float* d, const uint32_t* a, const uint32_t* b) {
    asm volatile(
        "mma.sync.aligned.m16n8k16.row.col.f32.bf16.bf16.f32 "
        "{%0,%1,%2,%3}, {%4,%5,%6,%7}, {%8,%9}, {%0,%1,%2,%3};"
        : "+f"(d[0]), "+f"(d[1]), "+f"(d[2]), "+f"(d[3])
        : "r"(a[0]), "r"(a[1]), "r"(a[2]), "r"(a[3]), "r"(b[0]), "r"(b[1]));
}

template <int K, int NC>
__global__ void __launch_bounds__(256) k_gemm_mma(
    const __nv_bfloat16* __restrict__ Ahi, const __nv_bfloat16* __restrict__ Alo,
    const __nv_bfloat16* __restrict__ Bhi, const __nv_bfloat16* __restrict__ Blo,
    const float* __restrict__ ASrc, const float* __restrict__ ADst,
    float* __restrict__ Cm, float* __restrict__ as_, float* __restrict__ ad_, int M)
{
    extern __shared__ char smc[];
    constexpr int AST  = 40;           // smem row stride in bf16
    constexpr int ABYT = 128 * AST * 2;   // 10240
    constexpr int BBYT = 64 * AST * 2;    // 5120
    constexpr int OFF_AH = 0;
    constexpr int OFF_AL = 2 * ABYT;
    constexpr int OFF_BH = 4 * ABYT;
    constexpr int OFF_BL = 4 * ABYT + 2 * BBYT;
    constexpr int CHUNKS = K / 32;

    const int tid  = threadIdx.x;
    const int lane = tid & 31;
    const int wid  = tid >> 5;
    const int wm   = wid & 3;
    const int wn   = wid >> 2;
    const int rowBase = blockIdx.x * 128;
    const int colBase = blockIdx.y * 64;
    const int g   = lane >> 2;
    const int tig = lane & 3;
    const uint32_t sbase = cvta_s(smc);

    float d[2][4][4];
#pragma unroll
    for (int mi = 0; mi < 2; mi++)
#pragma unroll
        for (int ni = 0; ni < 4; ni++)
#pragma unroll
            for (int q = 0; q < 4; q++) d[mi][ni][q] = 0.f;

    auto load_chunk = [&](int k0, int st) {
        uint32_t aH = sbase + OFF_AH + st * ABYT;
        uint32_t aL = sbase + OFF_AL + st * ABYT;
        uint32_t bH = sbase + OFF_BH + st * BBYT;
        uint32_t bL = sbase + OFF_BL + st * BBYT;
#pragma unroll
        for (int j = 0; j < 2; j++) {
            int i = tid + j * 256;       // 0..511
            int r = i >> 2, q = i & 3;
            int grow = rowBase + r;
            int cg = (grow < M) ? grow : 0;
            unsigned sz = (grow < M) ? 16u : 0u;
            size_t so = ((size_t)cg * K + k0) * 2 + q * 16;
            uint32_t dst = r * 80 + q * 16;
            cp_async16(aH + dst, (const char*)Ahi + so, sz);
            cp_async16(aL + dst, (const char*)Alo + so, sz);
        }
        {
            int r = tid >> 2, q = tid & 3;   // 64 rows x 4
            size_t so = ((size_t)(colBase + r) * K + k0) * 2 + q * 16;
            uint32_t dst = r * 80 + q * 16;
            cp_async16(bH + dst, (const char*)Bhi + so, 16u);
            cp_async16(bL + dst, (const char*)Blo + so, 16u);
        }
    };

    load_chunk(0, 0);
    CP_COMMIT();

    for (int c = 0; c < CHUNKS; c++) {
        if (c + 1 < CHUNKS) load_chunk((c + 1) * 32, (c + 1) & 1);
        CP_COMMIT();
        CP_WAIT1();
        __syncthreads();
        const int st = c & 1;
        const char* pAh = smc + OFF_AH + st * ABYT;
        const char* pAl = smc + OFF_AL + st * ABYT;
        const char* pBh = smc + OFF_BH + st * BBYT;
        const char* pBl = smc + OFF_BL + st * BBYT;
#pragma unroll
        for (int ks = 0; ks < 32; ks += 16) {
            uint32_t ah[2][4], al[2][4], bh[4][2], bl[4][2];
#pragma unroll
            for (int mi = 0; mi < 2; mi++) {
                int r0 = ((wm * 32 + mi * 16 + g) * AST + ks + 2 * tig) * 2;
                int r8 = r0 + 8 * AST * 2;
                ah[mi][0] = *(const uint32_t*)(pAh + r0);
                ah[mi][1] = *(const uint32_t*)(pAh + r8);
                ah[mi][2] = *(const uint32_t*)(pAh + r0 + 16);
                ah[mi][3] = *(const uint32_t*)(pAh + r8 + 16);
                al[mi][0] = *(const uint32_t*)(pAl + r0);
                al[mi][1] = *(const uint32_t*)(pAl + r8);
                al[mi][2] = *(const uint32_t*)(pAl + r0 + 16);
                al[mi][3] = *(const uint32_t*)(pAl + r8 + 16);
            }
#pragma unroll
            for (int ni = 0; ni < 4; ni++) {
                int br = ((wn * 32 + ni * 8 + g) * AST + ks + 2 * tig) * 2;
                bh[ni][0] = *(const uint32_t*)(pBh + br);
                bh[ni][1] = *(const uint32_t*)(pBh + br + 16);
                bl[ni][0] = *(const uint32_t*)(pBl + br);
                bl[ni][1] = *(const uint32_t*)(pBl + br + 16);
            }
#pragma unroll
            for (int mi = 0; mi < 2; mi++)
#pragma unroll
                for (int ni = 0; ni < 4; ni++) {
                    mma_bf16(d[mi][ni], ah[mi], bh[ni]);
                    mma_bf16(d[mi][ni], ah[mi], bl[ni]);
                    mma_bf16(d[mi][ni], al[mi], bh[ni]);
                }
        }
        __syncthreads();
    }

    // ---- write C
#pragma unroll
    for (int mi = 0; mi < 2; mi++) {
        int row0 = rowBase + wm * 32 + mi * 16 + g;
        int row8 = row0 + 8;
#pragma unroll
        for (int ni = 0; ni < 4; ni++) {
            int col = colBase + wn * 32 + ni * 8 + 2 * tig;
            if (row0 < M) {
                float2* p = (float2*)(Cm + (size_t)row0 * NC + col);
                *p = make_float2(d[mi][ni][0], d[mi][ni][1]);
            }
            if (row8 < M) {
                float2* p = (float2*)(Cm + (size_t)row8 * NC + col);
                *p = make_float2(d[mi][ni][2], d[mi][ni][3]);
            }
        }
    }

    // ---- fused attention coefficients for this block's 128 rows / 1 head
    const int head = (NC == 256) ? blockIdx.y : 0;
    float asv[4][2], adv[4][2];
#pragma unroll
    for (int ni = 0; ni < 4; ni++)
#pragma unroll
        for (int q = 0; q < 2; q++) {
            int c = wn * 32 + ni * 8 + 2 * tig + q;
            asv[ni][q] = ASrc[head * 64 + c];
            adv[ni][q] = ADst[head * 64 + c];
        }
    float vs[2][2], vd[2][2];
#pragma unroll
    for (int mi = 0; mi < 2; mi++)
#pragma unroll
        for (int hf = 0; hf < 2; hf++) {
            float ss = 0.f, dd = 0.f;
#pragma unroll
            for (int ni = 0; ni < 4; ni++) {
                ss += d[mi][ni][2 * hf] * asv[ni][0] + d[mi][ni][2 * hf + 1] * asv[ni][1];
                dd += d[mi][ni][2 * hf] * adv[ni][0] + d[mi][ni][2 * hf + 1] * adv[ni][1];
            }
#pragma unroll
            for (int off = 1; off < 4; off <<= 1) {
                ss += __shfl_xor_sync(0xffffffffu, ss, off);
                dd += __shfl_xor_sync(0xffffffffu, dd, off);
            }
            vs[mi][hf] = ss; vd[mi][hf] = dd;
        }
    float* sAS = (float*)smc;          // 128 floats
    float* sAD = (float*)(smc + 512);  // 128 floats
    __syncthreads();
    if (wn == 1 && tig == 0) {
#pragma unroll
        for (int mi = 0; mi < 2; mi++)
#pragma unroll
            for (int hf = 0; hf < 2; hf++) {
                int row = wm * 32 + mi * 16 + g + 8 * hf;
                sAS[row] = vs[mi][hf];
                sAD[row] = vd[mi][hf];
            }
    }
    __syncthreads();
    if (wn == 0 && tig == 0) {
#pragma unroll
        for (int mi = 0; mi < 2; mi++)
#pragma unroll
            for (int hf = 0; hf < 2; hf++) {
                int row = wm * 32 + mi * 16 + g + 8 * hf;
                int grow = rowBase + row;
                if (grow < M) {
                    float ts = vs[mi][hf] + sAS[row];
                    float td = vd[mi][hf] + sAD[row];
                    if (NC == 256) { as_[grow * 4 + head] = ts; ad_[grow * 4 + head] = td; }
                    else           { as_[grow] = ts; ad_[grow] = td; }
                }
            }
    }
}

// ---------------- warp-per-node softmax + aggregation (R9-exact) ----------------
template <int H, bool ELU, bool SPLIT>
__global__ void __launch_bounds__(256) k_agg_warp(
    const float* __restrict__ z, const int* __restrict__ srcs,
    const int* __restrict__ rowptr, const float* __restrict__ as_,
    const float* __restrict__ ad_, const float* __restrict__ bias,
    float* __restrict__ out,
    __nv_bfloat16* __restrict__ ohi, __nv_bfloat16* __restrict__ olo)
{
    __shared__ int   s_src[8][32];
    __shared__ float s_alpha[8][32 * H];

    const int wid  = threadIdx.x >> 5;
    const int lane = threadIdx.x & 31;
    const int n = blockIdx.x * 8 + wid;
    if (n >= N_NODES) return;

    const int start = rowptr[n];
    const int deg = rowptr[n + 1] - start;

    float m[H], s[H];
    float adv[H];
    if (H == 4) {
        float4 a = *(const float4*)(ad_ + n * 4);
        adv[0] = a.x; adv[1] = a.y; adv[2] = a.z; adv[3] = a.w;
    } else {
        adv[0] = ad_[n];
    }
#pragma unroll
    for (int h = 0; h < H; h++) { m[h] = -1e30f; s[h] = 0.f; }
    for (int j = lane; j < deg; j += 32) {
        int sidx = srcs[start + j];
        if (H == 4) {
            float4 av = *(const float4*)(as_ + sidx * 4);
            float ev[4] = {av.x, av.y, av.z, av.w};
#pragma unroll
            for (int h = 0; h < 4; h++) {
                float e = ev[h] + adv[h];
                e = (e > 0.f) ? e : 0.2f * e;
                float nm = fmaxf(m[h], e);
                s[h] = s[h] * __expf(m[h] - nm) + __expf(e - nm);
                m[h] = nm;
            }
        } else {
            float e = as_[sidx] + adv[0];
            e = (e > 0.f) ? e : 0.2f * e;
            float nm = fmaxf(m[0], e);
            s[0] = s[0] * __expf(m[0] - nm) + __expf(e - nm);
            m[0] = nm;
        }
    }
#pragma unroll
    for (int off = 16; off; off >>= 1) {
#pragma unroll
        for (int h = 0; h < H; h++) {
            float mo = __shfl_xor_sync(0xffffffffu, m[h], off);
            float so = __shfl_xor_sync(0xffffffffu, s[h], off);
            float nm = fmaxf(m[h], mo);
            s[h] = s[h] * __expf(m[h] - nm) + so * __expf(mo - nm);
            m[h] = nm;
        }
    }
#pragma unroll
    for (int h = 0; h < H; h++) s[h] = 1.0f / (s[h] + 1e-16f);

    float4 acc0 = make_float4(0.f, 0.f, 0.f, 0.f);
    float4 acc1 = make_float4(0.f, 0.f, 0.f, 0.f);
    float2 accs = make_float2(0.f, 0.f);
    const int head0 = lane >> 4;
    for (int base = 0; base < deg; base += 32) {
        int len = min(32, deg - base);
        if (lane < len) {
            int sidx = srcs[start + base + lane];
            s_src[wid][lane] = sidx;
            if (H == 4) {
                float4 av = *(const float4*)(as_ + sidx * 4);
                float ev[4] = {av.x, av.y, av.z, av.w};
#pragma unroll
                for (int h = 0; h < 4; h++) {
                    float e = ev[h] + adv[h];
                    e = (e > 0.f) ? e : 0.2f * e;
                    s_alpha[wid][lane * 4 + h] = __expf(e - m[h]) * s[h];
                }
            } else {
                float e = as_[sidx] + adv[0];
                e = (e > 0.f) ? e : 0.2f * e;
                s_alpha[wid][lane] = __expf(e - m[0]) * s[0];
            }
        }
        __syncwarp();
        if (H == 4) {
            for (int j = 0; j < len; j++) {
                int sidx = s_src[wid][j];
                float a0 = s_alpha[wid][j * 4 + head0];
                float a1 = s_alpha[wid][j * 4 + 2 + head0];
                const float4* zp = (const float4*)(z + (size_t)sidx * 256);
                float4 z0 = zp[lane];
                float4 z1 = zp[32 + lane];
                acc0.x = fmaf(a0, z0.x, acc0.x);
                acc0.y = fmaf(a0, z0.y, acc0.y);
                acc0.z = fmaf(a0, z0.z, acc0.z);
                acc0.w = fmaf(a0, z0.w, acc0.w);
                acc1.x = fmaf(a1, z1.x, acc1.x);
                acc1.y = fmaf(a1, z1.y, acc1.y);
                acc1.z = fmaf(a1, z1.z, acc1.z);
                acc1.w = fmaf(a1, z1.w, acc1.w);
            }
        } else {
            for (int j = 0; j < len; j++) {
                int sidx = s_src[wid][j];
                float a = s_alpha[wid][j];
                float2 zv = *(const float2*)(z + (size_t)sidx * 64 + lane * 2);
                accs.x = fmaf(a, zv.x, accs.x);
                accs.y = fmaf(a, zv.y, accs.y);
            }
        }
        __syncwarp();
    }

    if (H == 4) {
        float4 b0 = ((const float4*)bias)[lane];
        float4 b1 = ((const float4*)bias)[32 + lane];
        acc0.x += b0.x; acc0.y += b0.y; acc0.z += b0.z; acc0.w += b0.w;
        acc1.x += b1.x; acc1.y += b1.y; acc1.z += b1.z; acc1.w += b1.w;
        if (ELU) {
            acc0.x = (acc0.x > 0.f) ? acc0.x : expm1f(acc0.x);
            acc0.y = (acc0.y > 0.f) ? acc0.y : expm1f(acc0.y);
            acc0.z = (acc0.z > 0.f) ? acc0.z : expm1f(acc0.z);
            acc0.w = (acc0.w > 0.f) ? acc0.w : expm1f(acc0.w);
            acc1.x = (acc1.x > 0.f) ? acc1.x : expm1f(acc1.x);
            acc1.y = (acc1.y > 0.f) ? acc1.y : expm1f(acc1.y);
            acc1.z = (acc1.z > 0.f) ? acc1.z : expm1f(acc1.z);
            acc1.w = (acc1.w > 0.f) ? acc1.w : expm1f(acc1.w);
        }
        float4* po = (float4*)(out + (size_t)n * 256);
        po[lane] = acc0;
        po[32 + lane] = acc1;
        if (SPLIT) {
            __nv_bfloat16 h0x = __float2bfloat16(acc0.x), h0y = __float2bfloat16(acc0.y);
            __nv_bfloat16 h0z = __float2bfloat16(acc0.z), h0w = __float2bfloat16(acc0.w);
            __nv_bfloat16 h1x = __float2bfloat16(acc1.x), h1y = __float2bfloat16(acc1.y);
            __nv_bfloat16 h1z = __float2bfloat16(acc1.z), h1w = __float2bfloat16(acc1.w);
            __nv_bfloat162* ph = (__nv_bfloat162*)(ohi + (size_t)n * 256);
            __nv_bfloat162* pl = (__nv_bfloat162*)(olo + (size_t)n * 256);
            ph[2 * lane]     = __nv_bfloat162(h0x, h0y);
            ph[2 * lane + 1] = __nv_bfloat162(h0z, h0w);
            ph[64 + 2 * lane]     = __nv_bfloat162(h1x, h1y);
            ph[64 + 2 * lane + 1] = __nv_bfloat162(h1z, h1w);
            pl[2 * lane]     = __nv_bfloat162(__float2bfloat16(acc0.x - __bfloat162float(h0x)),
                                              __float2bfloat16(acc0.y - __bfloat162float(h0y)));
            pl[2 * lane + 1] = __nv_bfloat162(__float2bfloat16(acc0.z - __bfloat162float(h0z)),
                                              __float2bfloat16(acc0.w - __bfloat162float(h0w)));
            pl[64 + 2 * lane]     = __nv_bfloat162(__float2bfloat16(acc1.x - __bfloat162float(h1x)),
                                                   __float2bfloat16(acc1.y - __bfloat162float(h1y)));
            pl[64 + 2 * lane + 1] = __nv_bfloat162(__float2bfloat16(acc1.z - __bfloat162float(h1z)),
                                                   __float2bfloat16(acc1.w - __bfloat162float(h1w)));
        }
    } else {
        float2 b = ((const float2*)bias)[lane];
        accs.x += b.x; accs.y += b.y;
        if (ELU) {
            accs.x = (accs.x > 0.f) ? accs.x : expm1f(accs.x);
            accs.y = (accs.y > 0.f) ? accs.y : expm1f(accs.y);
        }
        *(float2*)(out + (size_t)n * 64 + lane * 2) = accs;
    }
}

// ---------------- segmented global max pool (batch is sorted) ----------------
__global__ void __launch_bounds__(256) k_pool_seg(
    const float* __restrict__ hfin, const int* __restrict__ batch,
    float* __restrict__ out)
{
    __shared__ float s_red[256];
    __shared__ int s_bounds[2];
    const int g = blockIdx.x;
    const int t = threadIdx.x;
    if (t < 2) {
        int target = g + t;
        int lo = 0, hi = N_NODES;
        while (lo < hi) {
            int mid = (lo + hi) >> 1;
            if (batch[mid] < target) lo = mid + 1; else hi = mid;
        }
        s_bounds[t] = lo;
    }
    __syncthreads();
    const int n0 = s_bounds[0], n1 = s_bounds[1];
    const int c = t & 63;
    const int sub = t >> 6;   // 0..3
    float acc = -1e30f;
    for (int n = n0 + sub; n < n1; n += 4)
        acc = fmaxf(acc, hfin[(size_t)n * 64 + c]);
    s_red[t] = acc;
    __syncthreads();
    if (t < 64) {
        float v = fmaxf(fmaxf(s_red[t], s_red[t + 64]),
                        fmaxf(s_red[t + 128], s_red[t + 192]));
        out[g * 64 + c] = v;
    }
}

// ---------------- launch ----------------
extern "C" void kernel_launch(void* const* d_in, const int* in_sizes, int n_in,
                              void* d_out, int out_size) {
    const float* x     = (const float*)d_in[0];
    const int*   ei    = (const int*)d_in[1];
    const int*   batch = (const int*)d_in[2];
    const float* W0    = (const float*)d_in[3];
    const float* AS0   = (const float*)d_in[4];
    const float* AD0   = (const float*)d_in[5];
    const float* B0    = (const float*)d_in[6];
    const float* W1    = (const float*)d_in[7];
    const float* AS1   = (const float*)d_in[8];
    const float* AD1   = (const float*)d_in[9];
    const float* B1    = (const float*)d_in[10];
    const float* W2    = (const float*)d_in[11];
    const float* AS2   = (const float*)d_in[12];
    const float* AD2   = (const float*)d_in[13];
    const float* B2    = (const float*)d_in[14];

    float *z, *h, *as_, *ad_;
    __nv_bfloat16 *ahi, *alo, *bh, *bl;
    int *rowptr, *cursor, *cnt, *srcs;
    cudaGetSymbolAddress((void**)&z, g_z);
    cudaGetSymbolAddress((void**)&h, g_h);
    cudaGetSymbolAddress((void**)&ahi, g_Ahi);
    cudaGetSymbolAddress((void**)&alo, g_Alo);
    cudaGetSymbolAddress((void**)&bh, g_Bh);
    cudaGetSymbolAddress((void**)&bl, g_Bl);
    cudaGetSymbolAddress((void**)&as_, g_as);
    cudaGetSymbolAddress((void**)&ad_, g_ad);
    cudaGetSymbolAddress((void**)&rowptr, g_rowptr);
    cudaGetSymbolAddress((void**)&cursor, g_cursor);
    cudaGetSymbolAddress((void**)&cnt, g_cnt);
    cudaGetSymbolAddress((void**)&srcs, g_srcs);

    // per-layer W buffer regions (hi/lo)
    __nv_bfloat16* bh0 = bh;            __nv_bfloat16* bl0 = bl;
    __nv_bfloat16* bh1 = bh + 16384;    __nv_bfloat16* bl1 = bl + 16384;
    __nv_bfloat16* bh2 = bh + 81920;    __nv_bfloat16* bl2 = bl + 81920;

    const int M = N_NODES;
    const int GEMM_GRID = (M + 127) / 128;   // 391
    const int AGG_GRID  = (N_NODES + 7) / 8; // warp-per-node, 8 warps/block
    const int GSMEM = 4 * 10240 + 4 * 5120;  // 61440 bytes

    cudaFuncSetAttribute(k_gemm_mma<64, 256>,  cudaFuncAttributeMaxDynamicSharedMemorySize, GSMEM);
    cudaFuncSetAttribute(k_gemm_mma<256, 256>, cudaFuncAttributeMaxDynamicSharedMemorySize, GSMEM);
    cudaFuncSetAttribute(k_gemm_mma<256, 64>,  cudaFuncAttributeMaxDynamicSharedMemorySize, GSMEM);

    // side stream + events (created once; launch pattern identical every call)
    static cudaStream_t sSide = nullptr;
    static cudaEvent_t  evRoot = nullptr, evSide = nullptr;
    if (!sSide) {
        cudaStreamCreateWithFlags(&sSide, cudaStreamNonBlocking);
        cudaEventCreateWithFlags(&evRoot, cudaEventDisableTiming);
        cudaEventCreateWithFlags(&evSide, cudaEventDisableTiming);
    }

    // ---- fork: CSR build + wsplit1/2 on side stream
    cudaEventRecord(evRoot, 0);
    cudaStreamWaitEvent(sSide, evRoot, 0);
    k_zero_cnt<<<(N_NODES + 255) / 256, 256, 0, sSide>>>(cnt);
    k_hist<<<(EP + 255) / 256, 256, 0, sSide>>>(ei, cnt);
    k_scan<<<1, 1024, 0, sSide>>>(cnt, rowptr, cursor);
    k_scatter<<<(EP + 255) / 256, 256, 0, sSide>>>(ei, cursor, srcs);
    k_wsplit<<<(256 * 256 + 255) / 256, 256, 0, sSide>>>(W1, bh1, bl1, 256, 256);
    k_wsplit<<<(256 * 64 + 255) / 256, 256, 0, sSide>>>(W2, bh2, bl2, 256, 64);
    cudaEventRecord(evSide, sSide);

    // ---- main stream: layer-0 prep + GEMM (independent of CSR)
    k_split<<<(N_NODES * 64 + 255) / 256, 256>>>(x, ahi, alo, N_NODES * 64);
    k_wsplit<<<(64 * 256 + 255) / 256, 256>>>(W0, bh0, bl0, 64, 256);
    k_gemm_mma<64, 256><<<dim3(GEMM_GRID, 4), 256, GSMEM>>>(ahi, alo, bh0, bl0, AS0, AD0, z, as_, ad_, M);

    // ---- join: agg needs CSR (and later layers need wsplit1/2)
    cudaStreamWaitEvent(0, evSide, 0);
    k_agg_warp<4, true, true><<<AGG_GRID, 256>>>(z, srcs, rowptr, as_, ad_, B0, h, ahi, alo);

    // ---- layer 1
    k_gemm_mma<256, 256><<<dim3(GEMM_GRID, 4), 256, GSMEM>>>(ahi, alo, bh1, bl1, AS1, AD1, z, as_, ad_, M);
    k_agg_warp<4, true, true><<<AGG_GRID, 256>>>(z, srcs, rowptr, as_, ad_, B1, h, ahi, alo);

    // ---- layer 2
    k_gemm_mma<256, 64><<<dim3(GEMM_GRID, 1), 256, GSMEM>>>(ahi, alo, bh2, bl2, AS2, AD2, z, as_, ad_, M);
    k_agg_warp<1, false, false><<<AGG_GRID, 256>>>(z, srcs, rowptr, as_, ad_, B2, h, (__nv_bfloat16*)0, (__nv_bfloat16*)0);

    // ---- segmented max pool
    k_pool_seg<<<GGR, 256>>>(h, batch, (float*)d_out);
}

// round 16
// speedup vs baseline: 1.4700x; 1.0080x over previous
#include <cuda_runtime.h>
#include <cuda_bf16.h>
#include <math.h>
#include <stdint.h>

#define N_NODES 50000
#define N_EDGES 800000
#define EP      (N_EDGES + N_NODES)   // with self loops = 850000
#define GGR     512
#define HID     64

// ---------------- scratch (device globals; no allocs allowed) ----------------
__device__ float    g_z[N_NODES * 256];
__device__ float    g_h[N_NODES * 256];
__device__ __nv_bfloat16 g_Ahi[N_NODES * 256];
__device__ __nv_bfloat16 g_Alo[N_NODES * 256];
__device__ __nv_bfloat16 g_Bh[96 * 1024];   // W0@0, W1@16384, W2@81920
__device__ __nv_bfloat16 g_Bl[96 * 1024];
__device__ float    g_as[N_NODES * 4];
__device__ float    g_ad[N_NODES * 4];
__device__ int      g_rowptr[N_NODES + 1];
__device__ int      g_cursor[N_NODES];
__device__ int      g_cnt[N_NODES];
__device__ int      g_srcs[EP];

// ---------------- small helpers ----------------
__device__ __forceinline__ uint32_t cvta_s(const void* p) {
    uint32_t a;
    asm("{ .reg .u64 t; cvta.to.shared.u64 t, %1; cvt.u32.u64 %0, t; }" : "=r"(a) : "l"(p));
    return a;
}
__device__ __forceinline__ void cp_async16(uint32_t dst, const void* src, unsigned sz) {
    asm volatile("cp.async.ca.shared.global [%0], [%1], 16, %2;"
                 :: "r"(dst), "l"(src), "r"(sz));
}
#define CP_COMMIT() asm volatile("cp.async.commit_group;" ::: "memory")
#define CP_WAIT1()  asm volatile("cp.async.wait_group 1;" ::: "memory")

// ---------------- CSR build ----------------
__global__ void k_zero_cnt(int* cnt) {
    int i = blockIdx.x * blockDim.x + threadIdx.x;
    if (i < N_NODES) cnt[i] = 0;
}

__global__ void k_hist(const int* __restrict__ ei, int* cnt) {
    int i = blockIdx.x * blockDim.x + threadIdx.x;
    if (i >= EP) return;
    int d = (i < N_EDGES) ? ei[N_EDGES + i] : (i - N_EDGES);
    atomicAdd(&cnt[d], 1);
}

// fast single-block scan: per-thread serial prefix + one warp/block shfl scan
__global__ void k_scan(const int* __restrict__ cnt, int* rowptr, int* cursor) {
    const int n = N_NODES;
    const int t = threadIdx.x;              // 1024 threads
    const int per = (n + 1023) / 1024;      // 49
    int b = t * per;
    int e = b + per; if (e > n) e = n;
    int sum = 0;
    for (int i = b; i < e; i++) sum += cnt[i];

    __shared__ int ws[32];
    int lane = t & 31, w = t >> 5;
    int inc = sum;
#pragma unroll
    for (int o = 1; o < 32; o <<= 1) {
        int v = __shfl_up_sync(0xffffffffu, inc, o);
        if (lane >= o) inc += v;
    }
    if (lane == 31) ws[w] = inc;
    __syncthreads();
    if (w == 0) {
        int iv = ws[lane];
#pragma unroll
        for (int o = 1; o < 32; o <<= 1) {
            int u = __shfl_up_sync(0xffffffffu, iv, o);
            if (lane >= o) iv += u;
        }
        ws[lane] = iv;
    }
    __syncthreads();
    int run = inc - sum + (w ? ws[w - 1] : 0);
    for (int i = b; i < e; i++) {
        rowptr[i] = run; cursor[i] = run;
        run += cnt[i];
    }
    if (b < n && e == n) rowptr[n] = run;
}

__global__ void k_scatter(const int* __restrict__ ei, int* cursor, int* srcs) {
    int i = blockIdx.x * blockDim.x + threadIdx.x;
    if (i >= EP) return;
    int s, d;
    if (i < N_EDGES) { s = ei[i]; d = ei[N_EDGES + i]; }
    else             { s = d = i - N_EDGES; }
    int p = atomicAdd(&cursor[d], 1);
    srcs[p] = s;
}

// ---------------- bf16 split helpers ----------------
__global__ void k_split(const float* __restrict__ a, __nv_bfloat16* __restrict__ hi,
                        __nv_bfloat16* __restrict__ lo, int n) {
    int i = blockIdx.x * blockDim.x + threadIdx.x;
    if (i >= n) return;
    float v = a[i];
    __nv_bfloat16 h = __float2bfloat16(v);
    hi[i] = h;
    lo[i] = __float2bfloat16(v - __bfloat162float(h));
}

// W[K,NC] row-major -> Bt[NC,K] hi/lo (col-major B for mma.sync)
__global__ void k_wsplit(const float* __restrict__ w, __nv_bfloat16* __restrict__ bh,
                         __nv_bfloat16* __restrict__ bl, int K, int NC) {
    int i = blockIdx.x * blockDim.x + threadIdx.x;
    if (i >= K * NC) return;
    int k = i / NC, n = i - k * NC;
    float v = w[i];
    __nv_bfloat16 h = __float2bfloat16(v);
    bh[n * K + k] = h;
    bl[n * K + k] = __float2bfloat16(v - __bfloat162float(h));
}

// ---------------- HMMA GEMM + fused attention coefficients ----------------
__device__ __forceinline__ void mma_bf16(float* d, const uint32_t* a, const uint32_t* b) {
    asm volatile(
        "mma.sync.aligned.m16n8k16.row.col.f32.bf16.bf16.f32 "
        "{%0,%1,%2,%3}, {%4,%5,%6,%7}, {%8,%9}, {%0,%1,%2,%3};"
        : "+f"(d[0]), "+f"(d[1]), "+f"(d[2]), "+f"(d[3])
        : "r"(a[0]), "r"(a[1]), "r"(a[2]), "r"(a[3]), "r"(b[0]), "r"(b[1]));
}

template <int K, int NC>
__global__ void __launch_bounds__(256) k_gemm_mma(
    const __nv_bfloat16* __restrict__ Ahi, const __nv_bfloat16* __restrict__ Alo,
    const __nv_bfloat16* __restrict__ Bhi, const __nv_bfloat16* __restrict__ Blo,
    const float* __restrict__ ASrc, const float* __restrict__ ADst,
    float* __restrict__ Cm, float* __restrict__ as_, float* __restrict__ ad_, int M)
{
    extern __shared__ char smc[];
    constexpr int AST  = 40;           // smem row stride in bf16
    constexpr int ABYT = 128 * AST * 2;   // 10240
    constexpr int BBYT = 64 * AST * 2;    // 5120
    constexpr int OFF_AH = 0;
    constexpr int OFF_AL = 2 * ABYT;
    constexpr int OFF_BH = 4 * ABYT;
    constexpr int OFF_BL = 4 * ABYT + 2 * BBYT;
    constexpr int CHUNKS = K / 32;

    const int tid  = threadIdx.x;
    const int lane = tid & 31;
    const int wid  = tid >> 5;
    const int wm   = wid & 3;
    const int wn   = wid >> 2;
    const int rowBase = blockIdx.x * 128;
    const int colBase = blockIdx.y * 64;
    const int g   = lane >> 2;
    const int tig = lane & 3;
    const uint32_t sbase = cvta_s(smc);

    float d[2][4][4];
#pragma unroll
    for (int mi = 0; mi < 2; mi++)
#pragma unroll
        for (int ni = 0; ni < 4; ni++)
#pragma unroll
            for (int q = 0; q < 4; q++) d[mi][ni][q] = 0.f;

    auto load_chunk = [&](int k0, int st) {
        uint32_t aH = sbase + OFF_AH + st * ABYT;
        uint32_t aL = sbase + OFF_AL + st * ABYT;
        uint32_t bH = sbase + OFF_BH + st * BBYT;
        uint32_t bL = sbase + OFF_BL + st * BBYT;
#pragma unroll
        for (int j = 0; j < 2; j++) {
            int i = tid + j * 256;       // 0..511
            int r = i >> 2, q = i & 3;
            int grow = rowBase + r;
            int cg = (grow < M) ? grow : 0;
            unsigned sz = (grow < M) ? 16u : 0u;
            size_t so = ((size_t)cg * K + k0) * 2 + q * 16;
            uint32_t dst = r * 80 + q * 16;
            cp_async16(aH + dst, (const char*)Ahi + so, sz);
            cp_async16(aL + dst, (const char*)Alo + so, sz);
        }
        {
            int r = tid >> 2, q = tid & 3;   // 64 rows x 4
            size_t so = ((size_t)(colBase + r) * K + k0) * 2 + q * 16;
            uint32_t dst = r * 80 + q * 16;
            cp_async16(bH + dst, (const char*)Bhi + so, 16u);
            cp_async16(bL + dst, (const char*)Blo + so, 16u);
        }
    };

    load_chunk(0, 0);
    CP_COMMIT();

    for (int c = 0; c < CHUNKS; c++) {
        if (c + 1 < CHUNKS) load_chunk((c + 1) * 32, (c + 1) & 1);
        CP_COMMIT();
        CP_WAIT1();
        __syncthreads();
        const int st = c & 1;
        const char* pAh = smc + OFF_AH + st * ABYT;
        const char* pAl = smc + OFF_AL + st * ABYT;
        const char* pBh = smc + OFF_BH + st * BBYT;
        const char* pBl = smc + OFF_BL + st * BBYT;
#pragma unroll
        for (int ks = 0; ks < 32; ks += 16) {
            uint32_t ah[2][4], al[2][4], bh[4][2], bl[4][2];
#pragma unroll
            for (int mi = 0; mi < 2; mi++) {
                int r0 = ((wm * 32 + mi * 16 + g) * AST + ks + 2 * tig) * 2;
                int r8 = r0 + 8 * AST * 2;
                ah[mi][0] = *(const uint32_t*)(pAh + r0);
                ah[mi][1] = *(const uint32_t*)(pAh + r8);
                ah[mi][2] = *(const uint32_t*)(pAh + r0 + 16);
                ah[mi][3] = *(const uint32_t*)(pAh + r8 + 16);
                al[mi][0] = *(const uint32_t*)(pAl + r0);
                al[mi][1] = *(const uint32_t*)(pAl + r8);
                al[mi][2] = *(const uint32_t*)(pAl + r0 + 16);
                al[mi][3] = *(const uint32_t*)(pAl + r8 + 16);
            }
#pragma unroll
            for (int ni = 0; ni < 4; ni++) {
                int br = ((wn * 32 + ni * 8 + g) * AST + ks + 2 * tig) * 2;
                bh[ni][0] = *(const uint32_t*)(pBh + br);
                bh[ni][1] = *(const uint32_t*)(pBh + br + 16);
                bl[ni][0] = *(const uint32_t*)(pBl + br);
                bl[ni][1] = *(const uint32_t*)(pBl + br + 16);
            }
#pragma unroll
            for (int mi = 0; mi < 2; mi++)
#pragma unroll
                for (int ni = 0; ni < 4; ni++) {
                    mma_bf16(d[mi][ni], ah[mi], bh[ni]);
                    mma_bf16(d[mi][ni], ah[mi], bl[ni]);
                    mma_bf16(d[mi][ni], al[mi], bh[ni]);
                }
        }
        __syncthreads();
    }

    // ---- write C
#pragma unroll
    for (int mi = 0; mi < 2; mi++) {
        int row0 = rowBase + wm * 32 + mi * 16 + g;
        int row8 = row0 + 8;
#pragma unroll
        for (int ni = 0; ni < 4; ni++) {
            int col = colBase + wn * 32 + ni * 8 + 2 * tig;
            if (row0 < M) {
                float2* p = (float2*)(Cm + (size_t)row0 * NC + col);
                *p = make_float2(d[mi][ni][0], d[mi][ni][1]);
            }
            if (row8 < M) {
                float2* p = (float2*)(Cm + (size_t)row8 * NC + col);
                *p = make_float2(d[mi][ni][2], d[mi][ni][3]);
            }
        }
    }

    // ---- fused attention coefficients for this block's 128 rows / 1 head
    const int head = (NC == 256) ? blockIdx.y : 0;
    float asv[4][2], adv[4][2];
#pragma unroll
    for (int ni = 0; ni < 4; ni++)
#pragma unroll
        for (int q = 0; q < 2; q++) {
            int c = wn * 32 + ni * 8 + 2 * tig + q;
            asv[ni][q] = ASrc[head * 64 + c];
            adv[ni][q] = ADst[head * 64 + c];
        }
    float vs[2][2], vd[2][2];
#pragma unroll
    for (int mi = 0; mi < 2; mi++)
#pragma unroll
        for (int hf = 0; hf < 2; hf++) {
            float ss = 0.f, dd = 0.f;
#pragma unroll
            for (int ni = 0; ni < 4; ni++) {
                ss += d[mi][ni][2 * hf] * asv[ni][0] + d[mi][ni][2 * hf + 1] * asv[ni][1];
                dd += d[mi][ni][2 * hf] * adv[ni][0] + d[mi][ni][2 * hf + 1] * adv[ni][1];
            }
#pragma unroll
            for (int off = 1; off < 4; off <<= 1) {
                ss += __shfl_xor_sync(0xffffffffu, ss, off);
                dd += __shfl_xor_sync(0xffffffffu, dd, off);
            }
            vs[mi][hf] = ss; vd[mi][hf] = dd;
        }
    float* sAS = (float*)smc;          // 128 floats
    float* sAD = (float*)(smc + 512);  // 128 floats
    __syncthreads();
    if (wn == 1 && tig == 0) {
#pragma unroll
        for (int mi = 0; mi < 2; mi++)
#pragma unroll
            for (int hf = 0; hf < 2; hf++) {
                int row = wm * 32 + mi * 16 + g + 8 * hf;
                sAS[row] = vs[mi][hf];
                sAD[row] = vd[mi][hf];
            }
    }
    __syncthreads();
    if (wn == 0 && tig == 0) {
#pragma unroll
        for (int mi = 0; mi < 2; mi++)
#pragma unroll
            for (int hf = 0; hf < 2; hf++) {
                int row = wm * 32 + mi * 16 + g + 8 * hf;
                int grow = rowBase + row;
                if (grow < M) {
                    float ts = vs[mi][hf] + sAS[row];
                    float td = vd[mi][hf] + sAD[row];
                    if (NC == 256) { as_[grow * 4 + head] = ts; ad_[grow * 4 + head] = td; }
                    else           { as_[grow] = ts; ad_[grow] = td; }
                }
            }
    }
}

// ---------------- warp-per-node softmax + aggregation ----------------
// SPLIT layers write ONLY the bf16 hi/lo splits (their fp32 out is never read).
template <int H, bool ELU, bool SPLIT>
__global__ void __launch_bounds__(256) k_agg_warp(
    const float* __restrict__ z, const int* __restrict__ srcs,
    const int* __restrict__ rowptr, const float* __restrict__ as_,
    const float* __restrict__ ad_, const float* __restrict__ bias,
    float* __restrict__ out,
    __nv_bfloat16* __restrict__ ohi, __nv_bfloat16* __restrict__ olo)
{
    __shared__ int   s_src[8][32];
    __shared__ float s_alpha[8][32 * H];

    const int wid  = threadIdx.x >> 5;
    const int lane = threadIdx.x & 31;
    const int n = blockIdx.x * 8 + wid;
    if (n >= N_NODES) return;

    const int start = rowptr[n];
    const int deg = rowptr[n + 1] - start;

    float m[H], s[H];
    float adv[H];
    if (H == 4) {
        float4 a = *(const float4*)(ad_ + n * 4);
        adv[0] = a.x; adv[1] = a.y; adv[2] = a.z; adv[3] = a.w;
    } else {
        adv[0] = ad_[n];
    }
#pragma unroll
    for (int h = 0; h < H; h++) { m[h] = -1e30f; s[h] = 0.f; }
    for (int j = lane; j < deg; j += 32) {
        int sidx = srcs[start + j];
        if (H == 4) {
            float4 av = *(const float4*)(as_ + sidx * 4);
            float ev[4] = {av.x, av.y, av.z, av.w};
#pragma unroll
            for (int h = 0; h < 4; h++) {
                float e = ev[h] + adv[h];
                e = (e > 0.f) ? e : 0.2f * e;
                float nm = fmaxf(m[h], e);
                s[h] = s[h] * __expf(m[h] - nm) + __expf(e - nm);
                m[h] = nm;
            }
        } else {
            float e = as_[sidx] + adv[0];
            e = (e > 0.f) ? e : 0.2f * e;
            float nm = fmaxf(m[0], e);
            s[0] = s[0] * __expf(m[0] - nm) + __expf(e - nm);
            m[0] = nm;
        }
    }
#pragma unroll
    for (int off = 16; off; off >>= 1) {
#pragma unroll
        for (int h = 0; h < H; h++) {
            float mo = __shfl_xor_sync(0xffffffffu, m[h], off);
            float so = __shfl_xor_sync(0xffffffffu, s[h], off);
            float nm = fmaxf(m[h], mo);
            s[h] = s[h] * __expf(m[h] - nm) + so * __expf(mo - nm);
            m[h] = nm;
        }
    }
#pragma unroll
    for (int h = 0; h < H; h++) s[h] = 1.0f / (s[h] + 1e-16f);

    float4 acc0 = make_float4(0.f, 0.f, 0.f, 0.f);
    float4 acc1 = make_float4(0.f, 0.f, 0.f, 0.f);
    float2 accs = make_float2(0.f, 0.f);
    const int head0 = lane >> 4;
    for (int base = 0; base < deg; base += 32) {
        int len = min(32, deg - base);
        if (lane < len) {
            int sidx = srcs[start + base + lane];
            s_src[wid][lane] = sidx;
            if (H == 4) {
                float4 av = *(const float4*)(as_ + sidx * 4);
                float ev[4] = {av.x, av.y, av.z, av.w};
#pragma unroll
                for (int h = 0; h < 4; h++) {
                    float e = ev[h] + adv[h];
                    e = (e > 0.f) ? e : 0.2f * e;
                    s_alpha[wid][lane * 4 + h] = __expf(e - m[h]) * s[h];
                }
            } else {
                float e = as_[sidx] + adv[0];
                e = (e > 0.f) ? e : 0.2f * e;
                s_alpha[wid][lane] = __expf(e - m[0]) * s[0];
            }
        }
        __syncwarp();
        if (H == 4) {
            for (int j = 0; j < len; j++) {
                int sidx = s_src[wid][j];
                float a0 = s_alpha[wid][j * 4 + head0];
                float a1 = s_alpha[wid][j * 4 + 2 + head0];
                const float4* zp = (const float4*)(z + (size_t)sidx * 256);
                float4 z0 = zp[lane];
                float4 z1 = zp[32 + lane];
                acc0.x = fmaf(a0, z0.x, acc0.x);
                acc0.y = fmaf(a0, z0.y, acc0.y);
                acc0.z = fmaf(a0, z0.z, acc0.z);
                acc0.w = fmaf(a0, z0.w, acc0.w);
                acc1.x = fmaf(a1, z1.x, acc1.x);
                acc1.y = fmaf(a1, z1.y, acc1.y);
                acc1.z = fmaf(a1, z1.z, acc1.z);
                acc1.w = fmaf(a1, z1.w, acc1.w);
            }
        } else {
            for (int j = 0; j < len; j++) {
                int sidx = s_src[wid][j];
                float a = s_alpha[wid][j];
                float2 zv = *(const float2*)(z + (size_t)sidx * 64 + lane * 2);
                accs.x = fmaf(a, zv.x, accs.x);
                accs.y = fmaf(a, zv.y, accs.y);
            }
        }
        __syncwarp();
    }

    if (H == 4) {
        float4 b0 = ((const float4*)bias)[lane];
        float4 b1 = ((const float4*)bias)[32 + lane];
        acc0.x += b0.x; acc0.y += b0.y; acc0.z += b0.z; acc0.w += b0.w;
        acc1.x += b1.x; acc1.y += b1.y; acc1.z += b1.z; acc1.w += b1.w;
        if (ELU) {
            acc0.x = (acc0.x > 0.f) ? acc0.x : expm1f(acc0.x);
            acc0.y = (acc0.y > 0.f) ? acc0.y : expm1f(acc0.y);
            acc0.z = (acc0.z > 0.f) ? acc0.z : expm1f(acc0.z);
            acc0.w = (acc0.w > 0.f) ? acc0.w : expm1f(acc0.w);
            acc1.x = (acc1.x > 0.f) ? acc1.x : expm1f(acc1.x);
            acc1.y = (acc1.y > 0.f) ? acc1.y : expm1f(acc1.y);
            acc1.z = (acc1.z > 0.f) ? acc1.z : expm1f(acc1.z);
            acc1.w = (acc1.w > 0.f) ? acc1.w : expm1f(acc1.w);
        }
        if (!SPLIT) {
            float4* po = (float4*)(out + (size_t)n * 256);
            po[lane] = acc0;
            po[32 + lane] = acc1;
        } else {
            __nv_bfloat16 h0x = __float2bfloat16(acc0.x), h0y = __float2bfloat16(acc0.y);
            __nv_bfloat16 h0z = __float2bfloat16(acc0.z), h0w = __float2bfloat16(acc0.w);
            __nv_bfloat16 h1x = __float2bfloat16(acc1.x), h1y = __float2bfloat16(acc1.y);
            __nv_bfloat16 h1z = __float2bfloat16(acc1.z), h1w = __float2bfloat16(acc1.w);
            __nv_bfloat162* ph = (__nv_bfloat162*)(ohi + (size_t)n * 256);
            __nv_bfloat162* pl = (__nv_bfloat162*)(olo + (size_t)n * 256);
            ph[2 * lane]     = __nv_bfloat162(h0x, h0y);
            ph[2 * lane + 1] = __nv_bfloat162(h0z, h0w);
            ph[64 + 2 * lane]     = __nv_bfloat162(h1x, h1y);
            ph[64 + 2 * lane + 1] = __nv_bfloat162(h1z, h1w);
            pl[2 * lane]     = __nv_bfloat162(__float2bfloat16(acc0.x - __bfloat162float(h0x)),
                                              __float2bfloat16(acc0.y - __bfloat162float(h0y)));
            pl[2 * lane + 1] = __nv_bfloat162(__float2bfloat16(acc0.z - __bfloat162float(h0z)),
                                              __float2bfloat16(acc0.w - __bfloat162float(h0w)));
            pl[64 + 2 * lane]     = __nv_bfloat162(__float2bfloat16(acc1.x - __bfloat162float(h1x)),
                                                   __float2bfloat16(acc1.y - __bfloat162float(h1y)));
            pl[64 + 2 * lane + 1] = __nv_bfloat162(__float2bfloat16(acc1.z - __bfloat162float(h1z)),
                                                   __float2bfloat16(acc1.w - __bfloat162float(h1w)));
        }
    } else {
        float2 b = ((const float2*)bias)[lane];
        accs.x += b.x; accs.y += b.y;
        if (ELU) {
            accs.x = (accs.x > 0.f) ? accs.x : expm1f(accs.x);
            accs.y = (accs.y > 0.f) ? accs.y : expm1f(accs.y);
        }
        *(float2*)(out + (size_t)n * 64 + lane * 2) = accs;
    }
}

// ---------------- segmented global max pool (batch is sorted) ----------------
__global__ void __launch_bounds__(256) k_pool_seg(
    const float* __restrict__ hfin, const int* __restrict__ batch,
    float* __restrict__ out)
{
    __shared__ float s_red[256];
    __shared__ int s_bounds[2];
    const int g = blockIdx.x;
    const int t = threadIdx.x;
    if (t < 2) {
        int target = g + t;
        int lo = 0, hi = N_NODES;
        while (lo < hi) {
            int mid = (lo + hi) >> 1;
            if (batch[mid] < target) lo = mid + 1; else hi = mid;
        }
        s_bounds[t] = lo;
    }
    __syncthreads();
    const int n0 = s_bounds[0], n1 = s_bounds[1];
    const int c = t & 63;
    const int sub = t >> 6;   // 0..3
    float acc = -1e30f;
    for (int n = n0 + sub; n < n1; n += 4)
        acc = fmaxf(acc, hfin[(size_t)n * 64 + c]);
    s_red[t] = acc;
    __syncthreads();
    if (t < 64) {
        float v = fmaxf(fmaxf(s_red[t], s_red[t + 64]),
                        fmaxf(s_red[t + 128], s_red[t + 192]));
        out[g * 64 + c] = v;
    }
}

// ---------------- launch ----------------
extern "C" void kernel_launch(void* const* d_in, const int* in_sizes, int n_in,
                              void* d_out, int out_size) {
    const float* x     = (const float*)d_in[0];
    const int*   ei    = (const int*)d_in[1];
    const int*   batch = (const int*)d_in[2];
    const float* W0    = (const float*)d_in[3];
    const float* AS0   = (const float*)d_in[4];
    const float* AD0   = (const float*)d_in[5];
    const float* B0    = (const float*)d_in[6];
    const float* W1    = (const float*)d_in[7];
    const float* AS1   = (const float*)d_in[8];
    const float* AD1   = (const float*)d_in[9];
    const float* B1    = (const float*)d_in[10];
    const float* W2    = (const float*)d_in[11];
    const float* AS2   = (const float*)d_in[12];
    const float* AD2   = (const float*)d_in[13];
    const float* B2    = (const float*)d_in[14];

    float *z, *h, *as_, *ad_;
    __nv_bfloat16 *ahi, *alo, *bh, *bl;
    int *rowptr, *cursor, *cnt, *srcs;
    cudaGetSymbolAddress((void**)&z, g_z);
    cudaGetSymbolAddress((void**)&h, g_h);
    cudaGetSymbolAddress((void**)&ahi, g_Ahi);
    cudaGetSymbolAddress((void**)&alo, g_Alo);
    cudaGetSymbolAddress((void**)&bh, g_Bh);
    cudaGetSymbolAddress((void**)&bl, g_Bl);
    cudaGetSymbolAddress((void**)&as_, g_as);
    cudaGetSymbolAddress((void**)&ad_, g_ad);
    cudaGetSymbolAddress((void**)&rowptr, g_rowptr);
    cudaGetSymbolAddress((void**)&cursor, g_cursor);
    cudaGetSymbolAddress((void**)&cnt, g_cnt);
    cudaGetSymbolAddress((void**)&srcs, g_srcs);

    // per-layer W buffer regions (hi/lo)
    __nv_bfloat16* bh0 = bh;            __nv_bfloat16* bl0 = bl;
    __nv_bfloat16* bh1 = bh + 16384;    __nv_bfloat16* bl1 = bl + 16384;
    __nv_bfloat16* bh2 = bh + 81920;    __nv_bfloat16* bl2 = bl + 81920;

    const int M = N_NODES;
    const int GEMM_GRID = (M + 127) / 128;   // 391
    const int AGG_GRID  = (N_NODES + 7) / 8; // warp-per-node, 8 warps/block
    const int GSMEM = 4 * 10240 + 4 * 5120;  // 61440 bytes

    cudaFuncSetAttribute(k_gemm_mma<64, 256>,  cudaFuncAttributeMaxDynamicSharedMemorySize, GSMEM);
    cudaFuncSetAttribute(k_gemm_mma<256, 256>, cudaFuncAttributeMaxDynamicSharedMemorySize, GSMEM);
    cudaFuncSetAttribute(k_gemm_mma<256, 64>,  cudaFuncAttributeMaxDynamicSharedMemorySize, GSMEM);

    // side stream + events (created once; launch pattern identical every call)
    static cudaStream_t sSide = nullptr;
    static cudaEvent_t  evRoot = nullptr, evSide = nullptr;
    if (!sSide) {
        cudaStreamCreateWithFlags(&sSide, cudaStreamNonBlocking);
        cudaEventCreateWithFlags(&evRoot, cudaEventDisableTiming);
        cudaEventCreateWithFlags(&evSide, cudaEventDisableTiming);
    }

    // ---- fork: CSR build + wsplit1/2 on side stream
    cudaEventRecord(evRoot, 0);
    cudaStreamWaitEvent(sSide, evRoot, 0);
    k_zero_cnt<<<(N_NODES + 255) / 256, 256, 0, sSide>>>(cnt);
    k_hist<<<(EP + 255) / 256, 256, 0, sSide>>>(ei, cnt);
    k_scan<<<1, 1024, 0, sSide>>>(cnt, rowptr, cursor);
    k_scatter<<<(EP + 255) / 256, 256, 0, sSide>>>(ei, cursor, srcs);
    k_wsplit<<<(256 * 256 + 255) / 256, 256, 0, sSide>>>(W1, bh1, bl1, 256, 256);
    k_wsplit<<<(256 * 64 + 255) / 256, 256, 0, sSide>>>(W2, bh2, bl2, 256, 64);
    cudaEventRecord(evSide, sSide);

    // ---- main stream: layer-0 prep + GEMM (independent of CSR)
    k_split<<<(N_NODES * 64 + 255) / 256, 256>>>(x, ahi, alo, N_NODES * 64);
    k_wsplit<<<(64 * 256 + 255) / 256, 256>>>(W0, bh0, bl0, 64, 256);
    k_gemm_mma<64, 256><<<dim3(GEMM_GRID, 4), 256, GSMEM>>>(ahi, alo, bh0, bl0, AS0, AD0, z, as_, ad_, M);

    // ---- join: agg needs CSR (and later layers need wsplit1/2)
    cudaStreamWaitEvent(0, evSide, 0);
    k_agg_warp<4, true, true><<<AGG_GRID, 256>>>(z, srcs, rowptr, as_, ad_, B0, h, ahi, alo);

    // ---- layer 1
    k_gemm_mma<256, 256><<<dim3(GEMM_GRID, 4), 256, GSMEM>>>(ahi, alo, bh1, bl1, AS1, AD1, z, as_, ad_, M);
    k_agg_warp<4, true, true><<<AGG_GRID, 256>>>(z, srcs, rowptr, as_, ad_, B1, h, ahi, alo);

    // ---- layer 2
    k_gemm_mma<256, 64><<<dim3(GEMM_GRID, 1), 256, GSMEM>>>(ahi, alo, bh2, bl2, AS2, AD2, z, as_, ad_, M);
    k_agg_warp<1, false, false><<<AGG_GRID, 256>>>(z, srcs, rowptr, as_, ad_, B2, h, (__nv_bfloat16*)0, (__nv_bfloat16*)0);

    // ---- segmented max pool
    k_pool_seg<<<GGR, 256>>>(h, batch, (float*)d_out);
}